// round 2
// baseline (speedup 1.0000x reference)
#include <cuda_runtime.h>
#include <cuda_bf16.h>

// Problem constants (fixed shapes for this problem)
#define B 32
#define C 3
#define H 640
#define W 640
#define POOL 8
#define CELL 80              // H/POOL
#define HIDDEN 64
#define FEAT (C*POOL*POOL)   // 192
#define NPARAM 15            // c*c + 2c
#define PLANE (H*W)          // 409600
#define PLANE4 (PLANE/4)     // 102400

// Scratch (allocation-free rule: __device__ globals)
__device__ float g_feat[B * FEAT];
__device__ float g_params[B * 16];

// ---------------------------------------------------------------------------
// Kernel 1: adaptive avg pool 640x640 -> 8x8 per (b,c).
// One block per (b, c, pool_row). Each of the 8 warps owns one 80x80 cell.
// ---------------------------------------------------------------------------
__global__ __launch_bounds__(256) void pool_kernel(const float* __restrict__ x,
                                                   float* __restrict__ feat) {
    int bid  = blockIdx.x;            // 0 .. B*C*POOL-1
    int pr   = bid & 7;
    int c    = (bid >> 3) % C;
    int b    = bid / (C * POOL);
    int warp = threadIdx.x >> 5;      // = pool col (pc)
    int lane = threadIdx.x & 31;

    const float* base = x + (((size_t)b * C + c) * H + (size_t)pr * CELL) * W
                        + (size_t)warp * CELL;
    const bool tail = (lane < 16);
    float s = 0.f;
    #pragma unroll 4
    for (int r = 0; r < CELL; ++r) {
        const float* rp = base + (size_t)r * W;
        // 80 columns, stride 32: lanes cover [0,32,64] offsets
        s += rp[lane];
        s += rp[lane + 32];
        if (tail) s += rp[lane + 64];
    }
    // warp reduce
    #pragma unroll
    for (int o = 16; o; o >>= 1) s += __shfl_xor_sync(0xFFFFFFFFu, s, o);
    if (lane == 0)
        feat[(b * C + c) * (POOL * POOL) + pr * POOL + warp] = s * (1.f / (CELL * CELL));
}

// ---------------------------------------------------------------------------
// Kernel 2: per-sample MLP: relu6(feat@W1+b1) @ W2 -> sigmoid -> 15 params.
// One block per sample, 64 threads (one per hidden unit).
// ---------------------------------------------------------------------------
__global__ __launch_bounds__(64) void mlp_kernel(const float* __restrict__ feat,
                                                 const float* __restrict__ W1,
                                                 const float* __restrict__ b1,
                                                 const float* __restrict__ W2,
                                                 float* __restrict__ params) {
    int b = blockIdx.x;
    int j = threadIdx.x;              // 0..63
    __shared__ float fs[FEAT];
    __shared__ float hs[HIDDEN];

    for (int k = j; k < FEAT; k += HIDDEN) fs[k] = feat[b * FEAT + k];
    __syncthreads();

    float acc = b1[j];
    #pragma unroll 8
    for (int k = 0; k < FEAT; ++k) acc = fmaf(fs[k], W1[k * HIDDEN + j], acc);
    hs[j] = fminf(fmaxf(acc, 0.f), 6.f);
    __syncthreads();

    if (j < NPARAM) {
        float a = 0.f;
        #pragma unroll 8
        for (int k = 0; k < HIDDEN; ++k) a = fmaf(hs[k], W2[k * NPARAM + j], a);
        params[b * 16 + j] = 1.f / (1.f + __expf(-a));
    }
}

// ---------------------------------------------------------------------------
// Kernel 3: per-pixel 3x3 color transform + gamma pow + normalize.
// float4 vectorized: each thread handles 4 pixels across all 3 channels.
// (r - mean)/std folded into fma with precomputed scale/shift.
// ---------------------------------------------------------------------------
__global__ __launch_bounds__(256) void transform_kernel(const float* __restrict__ x,
                                                        const float* __restrict__ params,
                                                        float* __restrict__ out) {
    const int b = blockIdx.y;
    __shared__ float p[16];
    if (threadIdx.x < 16) p[threadIdx.x] = params[b * 16 + threadIdx.x];
    __syncthreads();

    const float m00 = p[0], m01 = p[1], m02 = p[2];
    const float m10 = p[3], m11 = p[4], m12 = p[5];
    const float m20 = p[6], m21 = p[7], m22 = p[8];
    const float bi0 = p[9], bi1 = p[10], bi2 = p[11];
    const float g0  = p[12], g1 = p[13], g2 = p[14];

    const float s0 = 1.0f / 0.229f, s1 = 1.0f / 0.224f, s2 = 1.0f / 0.225f;
    const float t0 = -0.485f / 0.229f, t1 = -0.456f / 0.224f, t2 = -0.406f / 0.225f;

    int i4 = blockIdx.x * blockDim.x + threadIdx.x;   // 0 .. PLANE4-1
    const float4* xb = (const float4*)(x + (size_t)b * C * PLANE);
    float4* ob = (float4*)(out + (size_t)b * C * PLANE);

    float4 xa = xb[i4];
    float4 xc = xb[i4 + PLANE4];
    float4 xd = xb[i4 + 2 * PLANE4];

    float4 o0, o1, o2;
    #define DO_ELEM(FLD)                                                           \
    {                                                                              \
        float a = xa.FLD, bch = xc.FLD, cch = xd.FLD;                              \
        float y0 = fmaf(m00, a, fmaf(m01, bch, fmaf(m02, cch, bi0)));              \
        float y1 = fmaf(m10, a, fmaf(m11, bch, fmaf(m12, cch, bi1)));              \
        float y2 = fmaf(m20, a, fmaf(m21, bch, fmaf(m22, cch, bi2)));              \
        y0 = fmaxf(y0, 1e-20f); y1 = fmaxf(y1, 1e-20f); y2 = fmaxf(y2, 1e-20f);    \
        o0.FLD = fmaf(__powf(y0, g0), s0, t0);                                     \
        o1.FLD = fmaf(__powf(y1, g1), s1, t1);                                     \
        o2.FLD = fmaf(__powf(y2, g2), s2, t2);                                     \
    }
    DO_ELEM(x) DO_ELEM(y) DO_ELEM(z) DO_ELEM(w)
    #undef DO_ELEM

    ob[i4]              = o0;
    ob[i4 + PLANE4]     = o1;
    ob[i4 + 2 * PLANE4] = o2;
}

// ---------------------------------------------------------------------------
extern "C" void kernel_launch(void* const* d_in, const int* in_sizes, int n_in,
                              void* d_out, int out_size) {
    const float* x  = (const float*)d_in[0];   // (32,3,640,640)
    const float* W1 = (const float*)d_in[1];   // (192,64)
    const float* b1 = (const float*)d_in[2];   // (64,)
    const float* W2 = (const float*)d_in[3];   // (64,15)
    float* out = (float*)d_out;

    float* feat;   cudaGetSymbolAddress((void**)&feat,   g_feat);
    float* params; cudaGetSymbolAddress((void**)&params, g_params);

    pool_kernel<<<B * C * POOL, 256>>>(x, feat);
    mlp_kernel<<<B, HIDDEN>>>(feat, W1, b1, W2, params);
    dim3 grid(PLANE4 / 256, B);
    transform_kernel<<<grid, 256>>>(x, params, out);
}